// round 2
// baseline (speedup 1.0000x reference)
#include <cuda_runtime.h>
#include <cuda_bf16.h>
#include <cstdint>

#define BS   4096
#define NROW 8192
#define D    512
// exp(x/T) = 2^(x * log2(e)/T), T = 0.1
#define EXP_SCALE 14.426950408889634f
#define INV_T     10.0f

#define BM 128
#define BN 128
#define BK 64
#define SSTRIDE 72   // 64 data bf16 + 8 pad -> 144B row stride (conflict-free frag loads)

__device__ __nv_bfloat16 g_reps[(size_t)NROW * D];
__device__ float g_rowsum[NROW];
__device__ float g_pos[NROW];

__device__ __forceinline__ float fast_ex2(float x) {
    float r;
    asm("ex2.approx.ftz.f32 %0, %1;" : "=f"(r) : "f"(x));
    return r;
}

// One block per row: compute L2 norm, write bf16 normalized row, zero accumulators.
__global__ void normalize_kernel(const float* __restrict__ zi,
                                 const float* __restrict__ zj) {
    int row = blockIdx.x;
    const float* src = (row < BS) ? (zi + (size_t)row * D)
                                  : (zj + (size_t)(row - BS) * D);
    int t = threadIdx.x;  // 128 threads, 4 floats each
    float4 v = ((const float4*)src)[t];
    float ss = v.x * v.x + v.y * v.y + v.z * v.z + v.w * v.w;
    #pragma unroll
    for (int o = 16; o; o >>= 1) ss += __shfl_xor_sync(~0u, ss, o);
    __shared__ float wss[4];
    if ((t & 31) == 0) wss[t >> 5] = ss;
    __syncthreads();
    float total = wss[0] + wss[1] + wss[2] + wss[3];
    float inv = rsqrtf(total);  // norm ~ 22.6, clamp at 1e-8 never binds
    __nv_bfloat162* dst = (__nv_bfloat162*)(g_reps + (size_t)row * D);
    dst[2 * t + 0] = __floats2bfloat162_rn(v.x * inv, v.y * inv);
    dst[2 * t + 1] = __floats2bfloat162_rn(v.z * inv, v.w * inv);
    if (t == 0) { g_rowsum[row] = 0.0f; g_pos[row] = 0.0f; }
}

// Tiled bf16 MMA computing sim tiles with fused exp-row-sum epilogue.
// Block tile 128x128, K chunks of 64. 8 warps: 4 (M) x 2 (N), warp tile 32x64.
__global__ void __launch_bounds__(256, 2) sim_kernel() {
    __shared__ __nv_bfloat16 sA[BM * SSTRIDE];
    __shared__ __nv_bfloat16 sB[BN * SSTRIDE];

    const int bi = blockIdx.y, bj = blockIdx.x;
    const int t = threadIdx.x;
    const int warp = t >> 5, lane = t & 31;
    const int wm = warp >> 1, wn = warp & 1;

    float acc[2][8][4];
    #pragma unroll
    for (int mi = 0; mi < 2; mi++)
        #pragma unroll
        for (int ni = 0; ni < 8; ni++)
            #pragma unroll
            for (int c = 0; c < 4; c++) acc[mi][ni][c] = 0.0f;

    const int lr = t >> 3;   // 0..31 (row within 32-row pass)
    const int lc = t & 7;    // 0..7  (uint4 chunk within 64 cols)

    for (int kk = 0; kk < D; kk += BK) {
        __syncthreads();
        #pragma unroll
        for (int p = 0; p < 4; p++) {
            int r = lr + 32 * p;
            uint4 va = *(const uint4*)(g_reps + (size_t)(bi * BM + r) * D + kk + lc * 8);
            *(uint4*)(sA + r * SSTRIDE + lc * 8) = va;
            uint4 vb = *(const uint4*)(g_reps + (size_t)(bj * BN + r) * D + kk + lc * 8);
            *(uint4*)(sB + r * SSTRIDE + lc * 8) = vb;
        }
        __syncthreads();

        #pragma unroll
        for (int k16 = 0; k16 < BK; k16 += 16) {
            uint32_t a[2][4], b[8][2];
            const int arow = wm * 32 + (lane >> 2);
            const int acol = k16 + (lane & 3) * 2;
            #pragma unroll
            for (int mi = 0; mi < 2; mi++) {
                int rb = arow + mi * 16;
                a[mi][0] = *(const uint32_t*)(sA + (rb    ) * SSTRIDE + acol);
                a[mi][1] = *(const uint32_t*)(sA + (rb + 8) * SSTRIDE + acol);
                a[mi][2] = *(const uint32_t*)(sA + (rb    ) * SSTRIDE + acol + 8);
                a[mi][3] = *(const uint32_t*)(sA + (rb + 8) * SSTRIDE + acol + 8);
            }
            #pragma unroll
            for (int ni = 0; ni < 8; ni++) {
                int bn = wn * 64 + ni * 8 + (lane >> 2);
                int bk = k16 + (lane & 3) * 2;
                b[ni][0] = *(const uint32_t*)(sB + bn * SSTRIDE + bk);
                b[ni][1] = *(const uint32_t*)(sB + bn * SSTRIDE + bk + 8);
            }
            #pragma unroll
            for (int mi = 0; mi < 2; mi++)
                #pragma unroll
                for (int ni = 0; ni < 8; ni++) {
                    asm volatile(
                        "mma.sync.aligned.m16n8k16.row.col.f32.bf16.bf16.f32 "
                        "{%0,%1,%2,%3}, {%4,%5,%6,%7}, {%8,%9}, {%0,%1,%2,%3};\n"
                        : "+f"(acc[mi][ni][0]), "+f"(acc[mi][ni][1]),
                          "+f"(acc[mi][ni][2]), "+f"(acc[mi][ni][3])
                        : "r"(a[mi][0]), "r"(a[mi][1]), "r"(a[mi][2]), "r"(a[mi][3]),
                          "r"(b[ni][0]), "r"(b[ni][1]));
                }
        }
    }

    // Epilogue: exp(sim/T), skip diagonal, capture positives, reduce per row.
    float rp[4] = {0.f, 0.f, 0.f, 0.f};  // rows: +0, +8, +16, +24
    const int gi_base = bi * BM + wm * 32 + (lane >> 2);
    const int gj_base = bj * BN + wn * 64 + (lane & 3) * 2;
    #pragma unroll
    for (int mi = 0; mi < 2; mi++) {
        #pragma unroll
        for (int ni = 0; ni < 8; ni++) {
            #pragma unroll
            for (int c = 0; c < 4; c++) {
                int gi = gi_base + mi * 16 + (c >> 1) * 8;
                int gj = gj_base + ni * 8 + (c & 1);
                float val = acc[mi][ni][c];
                float e = fast_ex2(val * EXP_SCALE);
                if (gi != gj) rp[mi * 2 + (c >> 1)] += e;
                if (gj == (gi ^ BS)) g_pos[gi] = val;
            }
        }
    }
    #pragma unroll
    for (int r4 = 0; r4 < 4; r4++) {
        rp[r4] += __shfl_xor_sync(~0u, rp[r4], 1);
        rp[r4] += __shfl_xor_sync(~0u, rp[r4], 2);
    }
    if ((lane & 3) == 0) {
        int gi0 = bi * BM + wm * 32 + (lane >> 2);
        atomicAdd(&g_rowsum[gi0     ], rp[0]);
        atomicAdd(&g_rowsum[gi0 +  8], rp[1]);
        atomicAdd(&g_rowsum[gi0 + 16], rp[2]);
        atomicAdd(&g_rowsum[gi0 + 24], rp[3]);
    }
}

__global__ void loss_kernel(float* __restrict__ out) {
    int t = threadIdx.x;  // 256
    float s = 0.0f;
    for (int i = t; i < NROW; i += 256)
        s += logf(g_rowsum[i]) - g_pos[i] * INV_T;
    #pragma unroll
    for (int o = 16; o; o >>= 1) s += __shfl_xor_sync(~0u, s, o);
    __shared__ float wsum[8];
    if ((t & 31) == 0) wsum[t >> 5] = s;
    __syncthreads();
    if (t == 0) {
        float tot = 0.0f;
        #pragma unroll
        for (int w = 0; w < 8; w++) tot += wsum[w];
        out[0] = tot / (float)NROW;
    }
}

extern "C" void kernel_launch(void* const* d_in, const int* in_sizes, int n_in,
                              void* d_out, int out_size) {
    const float* zi = (const float*)d_in[0];
    const float* zj = (const float*)d_in[1];
    normalize_kernel<<<NROW, 128>>>(zi, zj);
    dim3 grid(NROW / BN, NROW / BM);
    sim_kernel<<<grid, 256>>>();
    loss_kernel<<<1, 256>>>((float*)d_out);
}

// round 4
// speedup vs baseline: 1.7325x; 1.7325x over previous
#include <cuda_runtime.h>
#include <cuda_bf16.h>
#include <cstdint>

#define BS   4096
#define NROW 8192
#define D    512
#define EXP_SCALE 14.426950408889634f   // log2(e)/0.1
#define INV_T     10.0f

#define BM 128
#define BN 128
#define BK 64
#define SSTRIDE 72        // 64 data bf16 + 8 pad
#define TILE_ELEMS (BM * SSTRIDE)
#define SMEM_BYTES (4 * TILE_ELEMS * 2)   // 2 buffers x (A+B) x bf16 = 73728 B
#define NTILE (NROW / BM)                  // 64
#define NBLOCKS (NTILE * (NTILE + 1) / 2)  // 2080

__device__ __nv_bfloat16 g_reps[(size_t)NROW * D];
__device__ float g_rowsum[NROW];
__device__ float g_pos[NROW];

__device__ __forceinline__ float fast_ex2(float x) {
    float r;
    asm("ex2.approx.ftz.f32 %0, %1;" : "=f"(r) : "f"(x));
    return r;
}

__device__ __forceinline__ void cp_async16(void* s, const void* g) {
    uint32_t saddr = (uint32_t)__cvta_generic_to_shared(s);
    asm volatile("cp.async.cg.shared.global [%0], [%1], 16;\n" :: "r"(saddr), "l"(g));
}

// One block per row: L2 norm -> bf16 normalized row, zero accumulators.
__global__ void normalize_kernel(const float* __restrict__ zi,
                                 const float* __restrict__ zj) {
    int row = blockIdx.x;
    const float* src = (row < BS) ? (zi + (size_t)row * D)
                                  : (zj + (size_t)(row - BS) * D);
    int t = threadIdx.x;  // 128 threads x 4 floats
    float4 v = ((const float4*)src)[t];
    float ss = v.x * v.x + v.y * v.y + v.z * v.z + v.w * v.w;
    #pragma unroll
    for (int o = 16; o; o >>= 1) ss += __shfl_xor_sync(~0u, ss, o);
    __shared__ float wss[4];
    if ((t & 31) == 0) wss[t >> 5] = ss;
    __syncthreads();
    float total = wss[0] + wss[1] + wss[2] + wss[3];
    float inv = rsqrtf(total);
    __nv_bfloat162* dst = (__nv_bfloat162*)(g_reps + (size_t)row * D);
    dst[2 * t + 0] = __floats2bfloat162_rn(v.x * inv, v.y * inv);
    dst[2 * t + 1] = __floats2bfloat162_rn(v.z * inv, v.w * inv);
    if (t == 0) { g_rowsum[row] = 0.0f; g_pos[row] = 0.0f; }
}

// Upper-triangular tiled bf16 MMA. Off-diagonal tiles contribute to both row
// and column sums (symmetry). cp.async double-buffered mainloop.
// 1-D grid of NBLOCKS CTAs; triangular decode of (bi, bj).
__global__ void __launch_bounds__(256, 2) sim_kernel() {
    // Decode linear tile id -> (bi, bj) with bj >= bi.
    // idx = bi*NTILE - bi*(bi-1)/2 + (bj - bi)
    int idx = blockIdx.x;
    float fi = (2.0f * NTILE + 1.0f
                - sqrtf((2.0f * NTILE + 1.0f) * (2.0f * NTILE + 1.0f)
                        - 8.0f * (float)idx)) * 0.5f;
    int bi = (int)fi;
    // guard float rounding
    while (bi * NTILE - (bi * (bi - 1)) / 2 > idx) bi--;
    while ((bi + 1) * NTILE - ((bi + 1) * bi) / 2 <= idx) bi++;
    int bj = bi + (idx - (bi * NTILE - (bi * (bi - 1)) / 2));

    extern __shared__ __nv_bfloat16 sm[];
    __nv_bfloat16* bufA[2] = { sm,                  sm + 2 * TILE_ELEMS };
    __nv_bfloat16* bufB[2] = { sm + TILE_ELEMS,     sm + 3 * TILE_ELEMS };

    const int t = threadIdx.x;
    const int warp = t >> 5, lane = t & 31;
    const int wm = warp >> 1, wn = warp & 1;
    const int lr = t >> 3;   // 0..31
    const int lc = t & 7;    // 0..7

    float acc[2][8][4];
    #pragma unroll
    for (int mi = 0; mi < 2; mi++)
        #pragma unroll
        for (int ni = 0; ni < 8; ni++)
            #pragma unroll
            for (int c = 0; c < 4; c++) acc[mi][ni][c] = 0.0f;

    // prefetch tile 0
    {
        #pragma unroll
        for (int p = 0; p < 4; p++) {
            int r = lr + 32 * p;
            cp_async16(bufA[0] + r * SSTRIDE + lc * 8,
                       g_reps + (size_t)(bi * BM + r) * D + lc * 8);
            cp_async16(bufB[0] + r * SSTRIDE + lc * 8,
                       g_reps + (size_t)(bj * BN + r) * D + lc * 8);
        }
        asm volatile("cp.async.commit_group;\n");
    }

    const int NIT = D / BK;   // 8
    for (int it = 0; it < NIT; it++) {
        if (it + 1 < NIT) {
            int nb = (it + 1) & 1, kk = (it + 1) * BK;
            #pragma unroll
            for (int p = 0; p < 4; p++) {
                int r = lr + 32 * p;
                cp_async16(bufA[nb] + r * SSTRIDE + lc * 8,
                           g_reps + (size_t)(bi * BM + r) * D + kk + lc * 8);
                cp_async16(bufB[nb] + r * SSTRIDE + lc * 8,
                           g_reps + (size_t)(bj * BN + r) * D + kk + lc * 8);
            }
            asm volatile("cp.async.commit_group;\n");
            asm volatile("cp.async.wait_group 1;\n");
        } else {
            asm volatile("cp.async.wait_group 0;\n");
        }
        __syncthreads();

        const __nv_bfloat16* sA = bufA[it & 1];
        const __nv_bfloat16* sB = bufB[it & 1];

        #pragma unroll
        for (int k16 = 0; k16 < BK; k16 += 16) {
            uint32_t a[2][4], b[8][2];
            const int arow = wm * 32 + (lane >> 2);
            const int acol = k16 + (lane & 3) * 2;
            #pragma unroll
            for (int mi = 0; mi < 2; mi++) {
                int rb = arow + mi * 16;
                a[mi][0] = *(const uint32_t*)(sA + (rb    ) * SSTRIDE + acol);
                a[mi][1] = *(const uint32_t*)(sA + (rb + 8) * SSTRIDE + acol);
                a[mi][2] = *(const uint32_t*)(sA + (rb    ) * SSTRIDE + acol + 8);
                a[mi][3] = *(const uint32_t*)(sA + (rb + 8) * SSTRIDE + acol + 8);
            }
            #pragma unroll
            for (int ni = 0; ni < 8; ni++) {
                int bn = wn * 64 + ni * 8 + (lane >> 2);
                int bk = k16 + (lane & 3) * 2;
                b[ni][0] = *(const uint32_t*)(sB + bn * SSTRIDE + bk);
                b[ni][1] = *(const uint32_t*)(sB + bn * SSTRIDE + bk + 8);
            }
            #pragma unroll
            for (int mi = 0; mi < 2; mi++)
                #pragma unroll
                for (int ni = 0; ni < 8; ni++) {
                    asm volatile(
                        "mma.sync.aligned.m16n8k16.row.col.f32.bf16.bf16.f32 "
                        "{%0,%1,%2,%3}, {%4,%5,%6,%7}, {%8,%9}, {%0,%1,%2,%3};\n"
                        : "+f"(acc[mi][ni][0]), "+f"(acc[mi][ni][1]),
                          "+f"(acc[mi][ni][2]), "+f"(acc[mi][ni][3])
                        : "r"(a[mi][0]), "r"(a[mi][1]), "r"(a[mi][2]), "r"(a[mi][3]),
                          "r"(b[ni][0]), "r"(b[ni][1]));
                }
        }
        __syncthreads();
    }

    // ---- Epilogue ----
    const int gi_base = bi * BM + wm * 32 + (lane >> 2);
    const int gj_base = bj * BN + wn * 64 + (lane & 3) * 2;

    if (bi == bj) {
        // diagonal tile: rows only, skip i==j
        float rp[4] = {0.f, 0.f, 0.f, 0.f};
        #pragma unroll
        for (int mi = 0; mi < 2; mi++)
            #pragma unroll
            for (int ni = 0; ni < 8; ni++)
                #pragma unroll
                for (int c = 0; c < 4; c++) {
                    int gi = gi_base + mi * 16 + (c >> 1) * 8;
                    int gj = gj_base + ni * 8 + (c & 1);
                    float e = fast_ex2(acc[mi][ni][c] * EXP_SCALE);
                    if (gi != gj) rp[mi * 2 + (c >> 1)] += e;
                }
        #pragma unroll
        for (int r4 = 0; r4 < 4; r4++) {
            rp[r4] += __shfl_xor_sync(~0u, rp[r4], 1);
            rp[r4] += __shfl_xor_sync(~0u, rp[r4], 2);
        }
        if ((lane & 3) == 0) {
            atomicAdd(&g_rowsum[gi_base     ], rp[0]);
            atomicAdd(&g_rowsum[gi_base +  8], rp[1]);
            atomicAdd(&g_rowsum[gi_base + 16], rp[2]);
            atomicAdd(&g_rowsum[gi_base + 24], rp[3]);
        }
    } else {
        // off-diagonal tile: rows AND columns (symmetry). i!=j always here.
        float rp[4] = {0.f, 0.f, 0.f, 0.f};
        float cs[8][2];
        #pragma unroll
        for (int ni = 0; ni < 8; ni++) { cs[ni][0] = 0.f; cs[ni][1] = 0.f; }
        const bool pos_tile = (bj == bi + BS / BM);   // bj == bi+32
        #pragma unroll
        for (int mi = 0; mi < 2; mi++)
            #pragma unroll
            for (int ni = 0; ni < 8; ni++)
                #pragma unroll
                for (int c = 0; c < 4; c++) {
                    int gi = gi_base + mi * 16 + (c >> 1) * 8;
                    int gj = gj_base + ni * 8 + (c & 1);
                    float val = acc[mi][ni][c];
                    float e = fast_ex2(val * EXP_SCALE);
                    rp[mi * 2 + (c >> 1)] += e;
                    cs[ni][c & 1] += e;
                    if (pos_tile && gj == gi + BS) {
                        g_pos[gi] = val;
                        g_pos[gj] = val;
                    }
                }
        // row reduce (across lane&3)
        #pragma unroll
        for (int r4 = 0; r4 < 4; r4++) {
            rp[r4] += __shfl_xor_sync(~0u, rp[r4], 1);
            rp[r4] += __shfl_xor_sync(~0u, rp[r4], 2);
        }
        if ((lane & 3) == 0) {
            atomicAdd(&g_rowsum[gi_base     ], rp[0]);
            atomicAdd(&g_rowsum[gi_base +  8], rp[1]);
            atomicAdd(&g_rowsum[gi_base + 16], rp[2]);
            atomicAdd(&g_rowsum[gi_base + 24], rp[3]);
        }
        // column reduce (across lane>>2)
        #pragma unroll
        for (int ni = 0; ni < 8; ni++) {
            #pragma unroll
            for (int p = 0; p < 2; p++) {
                cs[ni][p] += __shfl_xor_sync(~0u, cs[ni][p], 4);
                cs[ni][p] += __shfl_xor_sync(~0u, cs[ni][p], 8);
                cs[ni][p] += __shfl_xor_sync(~0u, cs[ni][p], 16);
            }
        }
        if ((lane >> 2) == 0) {
            #pragma unroll
            for (int ni = 0; ni < 8; ni++) {
                int gj = bj * BN + wn * 64 + ni * 8 + (lane & 3) * 2;
                atomicAdd(&g_rowsum[gj    ], cs[ni][0]);
                atomicAdd(&g_rowsum[gj + 1], cs[ni][1]);
            }
        }
    }
}

__global__ void loss_kernel(float* __restrict__ out) {
    int t = threadIdx.x;  // 1024
    float s = 0.0f;
    for (int i = t; i < NROW; i += 1024)
        s += logf(g_rowsum[i]) - g_pos[i] * INV_T;
    #pragma unroll
    for (int o = 16; o; o >>= 1) s += __shfl_xor_sync(~0u, s, o);
    __shared__ float wsum[32];
    if ((t & 31) == 0) wsum[t >> 5] = s;
    __syncthreads();
    if (t == 0) {
        float tot = 0.0f;
        #pragma unroll
        for (int w = 0; w < 32; w++) tot += wsum[w];
        out[0] = tot / (float)NROW;
    }
}

extern "C" void kernel_launch(void* const* d_in, const int* in_sizes, int n_in,
                              void* d_out, int out_size) {
    const float* zi = (const float*)d_in[0];
    const float* zj = (const float*)d_in[1];
    cudaFuncSetAttribute(sim_kernel, cudaFuncAttributeMaxDynamicSharedMemorySize,
                         SMEM_BYTES);
    normalize_kernel<<<NROW, 128>>>(zi, zj);
    sim_kernel<<<NBLOCKS, 256, SMEM_BYTES>>>();
    loss_kernel<<<1, 1024>>>((float*)d_out);
}

// round 6
// speedup vs baseline: 2.2007x; 1.2702x over previous
#include <cuda_runtime.h>
#include <cuda_bf16.h>
#include <cstdint>

#define BS   4096
#define NROW 8192
#define D    512
#define EXP_SCALE 14.426950408889634f   // log2(e)/0.1
#define INV_T     10.0f

#define BM 128
#define BN 128
#define BK 64
#define SSTRIDE 72        // 64 data bf16 + 8 pad
#define TILE_ELEMS (BM * SSTRIDE)
#define SMEM_BYTES (4 * TILE_ELEMS * 2)   // 2 buffers x (A+B) x bf16 = 73728 B
#define NTILE (NROW / BM)                  // 64
#define NBLOCKS (NTILE * (NTILE + 1) / 2)  // 2080

__device__ __nv_bfloat16 g_reps[(size_t)NROW * D];
__device__ float g_rowsum[NROW];
__device__ float g_pos[NROW];

__device__ __forceinline__ float fast_ex2(float x) {
    float r; asm("ex2.approx.ftz.f32 %0, %1;" : "=f"(r) : "f"(x)); return r;
}
__device__ __forceinline__ void cp_async16(void* s, const void* g) {
    uint32_t saddr = (uint32_t)__cvta_generic_to_shared(s);
    asm volatile("cp.async.cg.shared.global [%0], [%1], 16;\n" :: "r"(saddr), "l"(g));
}
__device__ __forceinline__ void ldsm_x4(uint32_t& r0, uint32_t& r1,
                                        uint32_t& r2, uint32_t& r3, uint32_t addr) {
    asm volatile("ldmatrix.sync.aligned.m8n8.x4.shared.b16 {%0,%1,%2,%3}, [%4];"
                 : "=r"(r0), "=r"(r1), "=r"(r2), "=r"(r3) : "r"(addr));
}

// -------------------- normalize --------------------
__global__ void normalize_kernel(const float* __restrict__ zi,
                                 const float* __restrict__ zj) {
    int row = blockIdx.x;
    const float* src = (row < BS) ? (zi + (size_t)row * D)
                                  : (zj + (size_t)(row - BS) * D);
    int t = threadIdx.x;  // 128 threads x 4 floats
    float4 v = ((const float4*)src)[t];
    float ss = v.x * v.x + v.y * v.y + v.z * v.z + v.w * v.w;
    #pragma unroll
    for (int o = 16; o; o >>= 1) ss += __shfl_xor_sync(~0u, ss, o);
    __shared__ float wss[4];
    if ((t & 31) == 0) wss[t >> 5] = ss;
    __syncthreads();
    float inv = rsqrtf(wss[0] + wss[1] + wss[2] + wss[3]);
    __nv_bfloat162* dst = (__nv_bfloat162*)(g_reps + (size_t)row * D);
    dst[2 * t + 0] = __floats2bfloat162_rn(v.x * inv, v.y * inv);
    dst[2 * t + 1] = __floats2bfloat162_rn(v.z * inv, v.w * inv);
    if (t == 0) { g_rowsum[row] = 0.0f; g_pos[row] = 0.0f; }
}

// -------------------- sim kernel (HMMA + ldmatrix) --------------------
__global__ void __launch_bounds__(256, 2) sim_kernel() {
    // triangular decode: linear id -> (bi, bj), bj >= bi
    int idx = blockIdx.x;
    float fi = (2.0f * NTILE + 1.0f
                - sqrtf((2.0f * NTILE + 1.0f) * (2.0f * NTILE + 1.0f)
                        - 8.0f * (float)idx)) * 0.5f;
    int bi = (int)fi;
    while (bi * NTILE - (bi * (bi - 1)) / 2 > idx) bi--;
    while ((bi + 1) * NTILE - ((bi + 1) * bi) / 2 <= idx) bi++;
    int bj = bi + (idx - (bi * NTILE - (bi * (bi - 1)) / 2));

    extern __shared__ __nv_bfloat16 sm[];
    __nv_bfloat16* bufA[2] = { sm,              sm + 2 * TILE_ELEMS };
    __nv_bfloat16* bufB[2] = { sm + TILE_ELEMS, sm + 3 * TILE_ELEMS };

    const int t = threadIdx.x;
    const int warp = t >> 5, lane = t & 31;
    const int wm = warp >> 1, wn = warp & 1;
    const int lr = t >> 3;   // 0..31 (cp.async row)
    const int lc = t & 7;    // 0..7  (cp.async 16B chunk)

    // ldmatrix lane-dependent element offsets (x2 for bytes applied at use)
    const int row_in = lane & 7, grp = lane >> 3;
    // A: per mi, 4 mats = {rows rb..rb+7 @k0, rb+8.. @k0, rb.. @k8, rb+8.. @k8}
    int offA[2];
    #pragma unroll
    for (int mi = 0; mi < 2; mi++)
        offA[mi] = (wm * 32 + mi * 16 + (grp & 1) * 8 + row_in) * SSTRIDE
                 + (grp >> 1) * 8;
    // B: per ni-pair p (ni=2p), 4 mats = {n-rows 2p*8 @k0, @k8, (2p+1)*8 @k0, @k8}
    int offB[4];
    #pragma unroll
    for (int p = 0; p < 4; p++)
        offB[p] = (wn * 64 + (2 * p + (grp >> 1)) * 8 + row_in) * SSTRIDE
                + (grp & 1) * 8;

    float acc[2][8][4];
    #pragma unroll
    for (int mi = 0; mi < 2; mi++)
        #pragma unroll
        for (int ni = 0; ni < 8; ni++)
            #pragma unroll
            for (int c = 0; c < 4; c++) acc[mi][ni][c] = 0.0f;

    // prefetch tile 0
    #pragma unroll
    for (int p = 0; p < 4; p++) {
        int r = lr + 32 * p;
        cp_async16(bufA[0] + r * SSTRIDE + lc * 8,
                   g_reps + (size_t)(bi * BM + r) * D + lc * 8);
        cp_async16(bufB[0] + r * SSTRIDE + lc * 8,
                   g_reps + (size_t)(bj * BN + r) * D + lc * 8);
    }
    asm volatile("cp.async.commit_group;\n");

    const int NIT = D / BK;   // 8
    for (int it = 0; it < NIT; it++) {
        if (it + 1 < NIT) {
            int nb = (it + 1) & 1, kk = (it + 1) * BK;
            #pragma unroll
            for (int p = 0; p < 4; p++) {
                int r = lr + 32 * p;
                cp_async16(bufA[nb] + r * SSTRIDE + lc * 8,
                           g_reps + (size_t)(bi * BM + r) * D + kk + lc * 8);
                cp_async16(bufB[nb] + r * SSTRIDE + lc * 8,
                           g_reps + (size_t)(bj * BN + r) * D + kk + lc * 8);
            }
            asm volatile("cp.async.commit_group;\n");
            asm volatile("cp.async.wait_group 1;\n");
        } else {
            asm volatile("cp.async.wait_group 0;\n");
        }
        __syncthreads();

        const uint32_t sA = (uint32_t)__cvta_generic_to_shared(bufA[it & 1]);
        const uint32_t sB = (uint32_t)__cvta_generic_to_shared(bufB[it & 1]);

        #pragma unroll
        for (int k16 = 0; k16 < BK; k16 += 16) {
            uint32_t a[2][4], b[8][2];
            #pragma unroll
            for (int mi = 0; mi < 2; mi++)
                ldsm_x4(a[mi][0], a[mi][1], a[mi][2], a[mi][3],
                        sA + (uint32_t)(offA[mi] + k16) * 2u);
            #pragma unroll
            for (int p = 0; p < 4; p++)
                ldsm_x4(b[2 * p][0], b[2 * p][1], b[2 * p + 1][0], b[2 * p + 1][1],
                        sB + (uint32_t)(offB[p] + k16) * 2u);
            #pragma unroll
            for (int mi = 0; mi < 2; mi++)
                #pragma unroll
                for (int ni = 0; ni < 8; ni++) {
                    asm volatile(
                        "mma.sync.aligned.m16n8k16.row.col.f32.bf16.bf16.f32 "
                        "{%0,%1,%2,%3}, {%4,%5,%6,%7}, {%8,%9}, {%0,%1,%2,%3};\n"
                        : "+f"(acc[mi][ni][0]), "+f"(acc[mi][ni][1]),
                          "+f"(acc[mi][ni][2]), "+f"(acc[mi][ni][3])
                        : "r"(a[mi][0]), "r"(a[mi][1]), "r"(a[mi][2]), "r"(a[mi][3]),
                          "r"(b[ni][0]), "r"(b[ni][1]));
                }
        }
        __syncthreads();
    }

    // ---- Epilogue ----
    const int gi_base = bi * BM + wm * 32 + (lane >> 2);
    const int gj_base = bj * BN + wn * 64 + (lane & 3) * 2;

    if (bi == bj) {
        float rp[4] = {0.f, 0.f, 0.f, 0.f};
        #pragma unroll
        for (int mi = 0; mi < 2; mi++)
            #pragma unroll
            for (int ni = 0; ni < 8; ni++)
                #pragma unroll
                for (int c = 0; c < 4; c++) {
                    int gi = gi_base + mi * 16 + (c >> 1) * 8;
                    int gj = gj_base + ni * 8 + (c & 1);
                    float e = fast_ex2(acc[mi][ni][c] * EXP_SCALE);
                    if (gi != gj) rp[mi * 2 + (c >> 1)] += e;
                }
        #pragma unroll
        for (int r4 = 0; r4 < 4; r4++) {
            rp[r4] += __shfl_xor_sync(~0u, rp[r4], 1);
            rp[r4] += __shfl_xor_sync(~0u, rp[r4], 2);
        }
        if ((lane & 3) == 0) {
            atomicAdd(&g_rowsum[gi_base     ], rp[0]);
            atomicAdd(&g_rowsum[gi_base +  8], rp[1]);
            atomicAdd(&g_rowsum[gi_base + 16], rp[2]);
            atomicAdd(&g_rowsum[gi_base + 24], rp[3]);
        }
    } else {
        float rp[4] = {0.f, 0.f, 0.f, 0.f};
        float cs[8][2];
        #pragma unroll
        for (int ni = 0; ni < 8; ni++) { cs[ni][0] = 0.f; cs[ni][1] = 0.f; }
        const bool pos_tile = (bj == bi + BS / BM);
        #pragma unroll
        for (int mi = 0; mi < 2; mi++)
            #pragma unroll
            for (int ni = 0; ni < 8; ni++)
                #pragma unroll
                for (int c = 0; c < 4; c++) {
                    int gi = gi_base + mi * 16 + (c >> 1) * 8;
                    int gj = gj_base + ni * 8 + (c & 1);
                    float val = acc[mi][ni][c];
                    float e = fast_ex2(val * EXP_SCALE);
                    rp[mi * 2 + (c >> 1)] += e;
                    cs[ni][c & 1] += e;
                    if (pos_tile && gj == gi + BS) {
                        g_pos[gi] = val;
                        g_pos[gj] = val;
                    }
                }
        #pragma unroll
        for (int r4 = 0; r4 < 4; r4++) {
            rp[r4] += __shfl_xor_sync(~0u, rp[r4], 1);
            rp[r4] += __shfl_xor_sync(~0u, rp[r4], 2);
        }
        if ((lane & 3) == 0) {
            atomicAdd(&g_rowsum[gi_base     ], rp[0]);
            atomicAdd(&g_rowsum[gi_base +  8], rp[1]);
            atomicAdd(&g_rowsum[gi_base + 16], rp[2]);
            atomicAdd(&g_rowsum[gi_base + 24], rp[3]);
        }
        #pragma unroll
        for (int ni = 0; ni < 8; ni++) {
            #pragma unroll
            for (int p = 0; p < 2; p++) {
                cs[ni][p] += __shfl_xor_sync(~0u, cs[ni][p], 4);
                cs[ni][p] += __shfl_xor_sync(~0u, cs[ni][p], 8);
                cs[ni][p] += __shfl_xor_sync(~0u, cs[ni][p], 16);
            }
        }
        if ((lane >> 2) == 0) {
            #pragma unroll
            for (int ni = 0; ni < 8; ni++) {
                int gj = bj * BN + wn * 64 + ni * 8 + (lane & 3) * 2;
                atomicAdd(&g_rowsum[gj    ], cs[ni][0]);
                atomicAdd(&g_rowsum[gj + 1], cs[ni][1]);
            }
        }
    }
}

// -------------------- loss --------------------
__global__ void loss_kernel(float* __restrict__ out) {
    int t = threadIdx.x;  // 1024
    float s = 0.0f;
    for (int i = t; i < NROW; i += 1024)
        s += logf(g_rowsum[i]) - g_pos[i] * INV_T;
    #pragma unroll
    for (int o = 16; o; o >>= 1) s += __shfl_xor_sync(~0u, s, o);
    __shared__ float wsum[32];
    if ((t & 31) == 0) wsum[t >> 5] = s;
    __syncthreads();
    if (t == 0) {
        float tot = 0.0f;
        #pragma unroll
        for (int w = 0; w < 32; w++) tot += wsum[w];
        out[0] = tot / (float)NROW;
    }
}

extern "C" void kernel_launch(void* const* d_in, const int* in_sizes, int n_in,
                              void* d_out, int out_size) {
    const float* zi = (const float*)d_in[0];
    const float* zj = (const float*)d_in[1];
    cudaFuncSetAttribute(sim_kernel, cudaFuncAttributeMaxDynamicSharedMemorySize,
                         SMEM_BYTES);
    normalize_kernel<<<NROW, 128>>>(zi, zj);
    sim_kernel<<<NBLOCKS, 256, SMEM_BYTES>>>();
    loss_kernel<<<1, 1024>>>((float*)d_out);
}